// round 15
// baseline (speedup 1.0000x reference)
#include <cuda_runtime.h>
#include <cstdint>

#define N_NODES 50000
#define N_EDGES 800000
#define F_X 128
#define F_E 128
#define HIDDEN 512
#define F_OUT 128
#define M_BLKS 3128                    // 50048 rows: pads 50000 to 128-row CTAs

// ---------------- scratch (static device globals; no runtime alloc) --------
// FRAG-A layout: word(r,c) = ((r>>4)*(K/8) + (c>>3))*128
//                            + (4*(r&7)+(c&3))*4 + ((c>>2)&1)*2 + ((r>>3)&1)
// FRAG-B layout: word(n,k) = ((n>>3)*(K/16) + (k>>4))*128
//                            + (4*(n&7)+(k&3))*4 + ((k>>3)&1)*2 + ((k>>2)&1)
__device__ float    g_agg[(size_t)N_NODES * F_E];                 // 25.6 MB
__device__ uint32_t g_A[(size_t)M_BLKS * 32 * 128];               // 51.3 MB, K=256
__device__ uint32_t g_h[(size_t)M_BLKS * 64 * 128];               // 102.5 MB, K=512
__device__ uint32_t g_W1t[(size_t)HIDDEN * (F_E + F_X)];          // FRAG-B K=256
__device__ uint32_t g_W2t[(size_t)F_OUT * HIDDEN];                // FRAG-B K=512

__device__ __forceinline__ uint32_t f2tf32(float f) {
    uint32_t r; asm("cvt.rna.tf32.f32 %0, %1;" : "=r"(r) : "f"(f)); return r;
}
__device__ __forceinline__ uint32_t smem_u32(const void* p) {
    uint32_t a;
    asm("{ .reg .u64 t; cvta.to.shared.u64 t, %1; cvt.u32.u64 %0, t; }"
        : "=r"(a) : "l"(p));
    return a;
}

// ---------------------------------------------------------------------------
// scatter-add, one warp per edge, red.global.add.v4.f32  (at DRAM floor)
// ---------------------------------------------------------------------------
__global__ void __launch_bounds__(256) scatter_edges_kernel(
    const float4* __restrict__ edge_attr, const int* __restrict__ receivers)
{
    int gt = blockIdx.x * blockDim.x + threadIdx.x;
    int edge = gt >> 5;
    int lane = gt & 31;
    if (edge >= N_EDGES) return;

    int r = __ldg(receivers + edge);
    float4 v = edge_attr[(size_t)edge * 32 + lane];
    float* dst = g_agg + (size_t)r * F_E + lane * 4;
    asm volatile("red.global.add.v4.f32 [%0], {%1,%2,%3,%4};"
                 :: "l"(dst), "f"(v.x), "f"(v.y), "f"(v.z), "f"(v.w)
                 : "memory");
}

// ---------------------------------------------------------------------------
// prep v2: fully-coalesced FRAG builds.
//  blocks [0, 3125)        : A tile transpose — 16 rows x 256 cols per CTA
//  blocks [3125, 3253)     : W1 FRAG-B chunks (256/CTA)
//  blocks [3253, 3317)     : W2 FRAG-B chunks (256/CTA)
// ---------------------------------------------------------------------------
#define PREP_ABLK  3125
#define PREP_W1BLK 128           // 32768 chunks / 256
#define PREP_W2BLK 64            // 16384 chunks / 256
#define PREP_BLKS  (PREP_ABLK + PREP_W1BLK + PREP_W2BLK)

__global__ void __launch_bounds__(256) prep_kernel(
    const float* __restrict__ nodes,
    const float* __restrict__ W1, const float* __restrict__ W2)
{
    int blk = blockIdx.x;
    int tid = threadIdx.x;

    if (blk < PREP_ABLK) {
        __shared__ uint32_t s[16 * 260];       // stride 260: LDS bank = 4g+t4
        int a = blk;
        // coalesced load: 16 rows x 256 cols (agg cols 0-127, nodes 128-255)
        #pragma unroll
        for (int i = 0; i < 4; ++i) {
            int e = tid + i * 256;             // 0..1023 float4
            int r = e >> 6, c = (e & 63) * 4;
            const float* src = (c < F_E)
                ? (g_agg + (size_t)(a * 16 + r) * F_E + c)
                : (nodes + (size_t)(a * 16 + r) * F_X + (c - F_E));
            float4 v = *reinterpret_cast<const float4*>(src);
            uint4 t;
            t.x = f2tf32(v.x); t.y = f2tf32(v.y);
            t.z = f2tf32(v.z); t.w = f2tf32(v.w);
            *reinterpret_cast<uint4*>(&s[r * 260 + c]) = t;
        }
        __syncthreads();
        // conflict-free gather -> coalesced STG.128 chunk writes
        #pragma unroll
        for (int i = 0; i < 4; ++i) {
            int e = tid + i * 256;             // 0..1023 chunks
            int b = e >> 5, l = e & 31;
            int gg = l >> 2, t4 = l & 3;
            int c = b * 8 + t4;
            uint4 t;
            t.x = s[gg * 260 + c];
            t.y = s[(gg + 8) * 260 + c];
            t.z = s[gg * 260 + c + 4];
            t.w = s[(gg + 8) * 260 + c + 4];
            reinterpret_cast<uint4*>(g_A)[(size_t)a * 1024 + e] = t;
        }
    } else if (blk < PREP_ABLK + PREP_W1BLK) {
        int idx = (blk - PREP_ABLK) * 256 + tid;      // 0..32767
        int cb = idx >> 5, l = idx & 31;
        int n8 = cb >> 4, kb = cb & 15;               // K/16 = 16
        int n = n8 * 8 + (l >> 2), t4 = l & 3;
        int k0 = kb * 16 + t4;
        uint4 t;
        t.x = f2tf32(W1[(size_t)(k0     ) * HIDDEN + n]);
        t.y = f2tf32(W1[(size_t)(k0 +  4) * HIDDEN + n]);
        t.z = f2tf32(W1[(size_t)(k0 +  8) * HIDDEN + n]);
        t.w = f2tf32(W1[(size_t)(k0 + 12) * HIDDEN + n]);
        reinterpret_cast<uint4*>(g_W1t)[idx] = t;
    } else {
        int idx = (blk - PREP_ABLK - PREP_W1BLK) * 256 + tid;  // 0..16383
        int cb = idx >> 5, l = idx & 31;
        int n8 = cb >> 5, kb = cb & 31;               // K/16 = 32
        int n = n8 * 8 + (l >> 2), t4 = l & 3;
        int k0 = kb * 16 + t4;
        uint4 t;
        t.x = f2tf32(W2[(size_t)(k0     ) * F_OUT + n]);
        t.y = f2tf32(W2[(size_t)(k0 +  4) * F_OUT + n]);
        t.z = f2tf32(W2[(size_t)(k0 +  8) * F_OUT + n]);
        t.w = f2tf32(W2[(size_t)(k0 + 12) * F_OUT + n]);
        reinterpret_cast<uint4*>(g_W2t)[idx] = t;
    }
}

// ---------------------------------------------------------------------------
// cp.async 3-stage tf32 mma GEMM on FRAG-major operands (mainloop unchanged).
// Unified shape: BM=128, BN=64, BK=32; 8 warps 4m x 2n (warp 32x32), MT=2.
// 3 CTAs/SM (launch_bounds(256,3), 73.7 KB smem).
// L1=true : K=256, A=g_A, out=g_h FRAG-A via SMEM-staged STG.128. grid (8,391)
// L1=false: K=512, A=g_h, out=Cout fp32 row-major direct.        grid (2,391)
// ---------------------------------------------------------------------------
template <bool L1>
__global__ void __launch_bounds__(256, 3)
gemm_frag_kernel(const uint32_t* __restrict__ Aglob,
                 const uint32_t* __restrict__ Bglob,
                 const float* __restrict__ bias,
                 float* __restrict__ Cout)
{
    constexpr int K   = L1 ? 256 : 512;
    constexpr int BN  = 64;
    constexpr int MT  = 2;
    constexpr int NTILES = K / 32;
    constexpr int A_STW  = 128 * 32;                // 4096 words
    constexpr int B_STW  = BN * 32;                 // 2048 words
    constexpr int STW    = A_STW + B_STW;           // 6144 words / stage
    constexpr int KB8    = K / 8;
    constexpr int KB16   = K / 16;

    extern __shared__ uint32_t smem[];
    const uint32_t sbase = smem_u32(smem);

    const int tid  = threadIdx.x;
    const int lane = tid & 31;
    const int warp = tid >> 5;
    const int m0 = blockIdx.y * 128;
    const int n0 = blockIdx.x * BN;
    const int warp_m = (warp >> 1) * 32;
    const int warp_n = (warp & 1) * 32;
    const int g  = lane >> 2;
    const int t4 = lane & 3;

    float acc[MT][4][4];
    #pragma unroll
    for (int mt = 0; mt < MT; ++mt)
        #pragma unroll
        for (int nt = 0; nt < 4; ++nt)
            #pragma unroll
            for (int i = 0; i < 4; ++i) acc[mt][nt][i] = 0.f;

    auto issue = [&](int tile, int slot) {
        const int kb8  = tile * 4;
        const int kb16 = tile * 2;
        uint32_t ab = sbase + (uint32_t)(slot * STW) * 4;
        uint32_t bb = ab + A_STW * 4;
        #pragma unroll
        for (int i = 0; i < 4; ++i) {                 // A: 1024 chunks
            int e = tid + i * 256;
            int a_l = e >> 7, b_l = (e >> 5) & 3, l = e & 31;
            const uint32_t* src = Aglob +
                ((size_t)((m0 >> 4) + a_l) * KB8 + kb8 + b_l) * 128 + l * 4;
            asm volatile("cp.async.cg.shared.global [%0], [%1], 16;"
                :: "r"(ab + (uint32_t)(((a_l * 4 + b_l) * 32 + l) * 16)),
                   "l"(src) : "memory");
        }
        #pragma unroll
        for (int i = 0; i < 2; ++i) {                 // B: 512 chunks
            int e = tid + i * 256;
            int n_l = e >> 6, p = (e >> 5) & 1, l = e & 31;
            const uint32_t* src = Bglob +
                ((size_t)((n0 >> 3) + n_l) * KB16 + kb16 + p) * 128 + l * 4;
            asm volatile("cp.async.cg.shared.global [%0], [%1], 16;"
                :: "r"(bb + (uint32_t)(((n_l * 2 + p) * 32 + l) * 16)),
                   "l"(src) : "memory");
        }
    };

    issue(0, 0); asm volatile("cp.async.commit_group;" ::: "memory");
    issue(1, 1); asm volatile("cp.async.commit_group;" ::: "memory");

    for (int it = 0; it < NTILES; ++it) {
        asm volatile("cp.async.wait_group 1;" ::: "memory");
        __syncthreads();
        // single barrier: all warps finished compute(it-1); slot (it+2)%3
        // == (it-1)%3 is safe to overwrite.
        if (it + 2 < NTILES) issue(it + 2, (it + 2) % 3);
        asm volatile("cp.async.commit_group;" ::: "memory");

        const uint4* As4 = reinterpret_cast<const uint4*>(smem + (it % 3) * STW);
        const uint4* Bs4 = As4 + A_STW / 4;

        #pragma unroll
        for (int p = 0; p < 2; ++p) {                  // k16 pair
            uint4 bfr[4];
            #pragma unroll
            for (int nt = 0; nt < 4; ++nt) {
                int n_l = (warp_n >> 3) + nt;
                bfr[nt] = Bs4[(n_l * 2 + p) * 32 + lane];
            }
            #pragma unroll
            for (int half = 0; half < 2; ++half) {
                const int ks = p * 2 + half;
                uint4 afr[MT];
                #pragma unroll
                for (int mt = 0; mt < MT; ++mt) {
                    int a_l = (warp_m >> 4) + mt;
                    afr[mt] = As4[(a_l * 4 + ks) * 32 + lane];
                }
                #pragma unroll
                for (int mt = 0; mt < MT; ++mt)
                    #pragma unroll
                    for (int nt = 0; nt < 4; ++nt) {
                        uint32_t b0 = half ? bfr[nt].z : bfr[nt].x;
                        uint32_t b1 = half ? bfr[nt].w : bfr[nt].y;
                        asm volatile(
                            "mma.sync.aligned.m16n8k8.row.col.f32.tf32.tf32.f32 "
                            "{%0,%1,%2,%3}, {%4,%5,%6,%7}, {%8,%9}, {%0,%1,%2,%3};"
                            : "+f"(acc[mt][nt][0]), "+f"(acc[mt][nt][1]),
                              "+f"(acc[mt][nt][2]), "+f"(acc[mt][nt][3])
                            : "r"(afr[mt].x), "r"(afr[mt].y),
                              "r"(afr[mt].z), "r"(afr[mt].w),
                              "r"(b0), "r"(b1));
                    }
            }
        }
    }

    if (L1) {
        // ---- SMEM-staged FRAG-A epilogue: scattered STS, coalesced STG.128.
        // g_h is padded to 50048 rows (= 391*128), so no row mask needed.
        __syncthreads();                    // stage-buffer reads complete
        uint32_t* st = smem;                // 8192 words (64 blk x 128)
        #pragma unroll
        for (int mt = 0; mt < MT; ++mt) {
            #pragma unroll
            for (int nt = 0; nt < 4; ++nt) {
                int gcl = warp_n + nt * 8 + t4 * 2;        // 0..63, even
                float2 bv = *reinterpret_cast<const float2*>(bias + n0 + gcl);
                #pragma unroll
                for (int hh = 0; hh < 2; ++hh) {
                    int grl = warp_m + mt * 16 + g + hh * 8;   // 0..127
                    uint32_t tx = f2tf32(fmaxf(acc[mt][nt][hh * 2 + 0] + bv.x, 0.f));
                    uint32_t ty = f2tf32(fmaxf(acc[mt][nt][hh * 2 + 1] + bv.y, 0.f));
                    int blk = ((grl >> 4) << 3) + (gcl >> 3);
                    int wr  = (grl >> 3) & 1;
                    int base = blk * 128 + (4 * (grl & 7)) * 4 + wr;
                    st[base + (gcl & 3) * 4 + ((gcl >> 2) & 1) * 2] = tx;
                    int gc1 = gcl + 1;
                    st[base + (gc1 & 3) * 4 + ((gc1 >> 2) & 1) * 2] = ty;
                }
            }
        }
        __syncthreads();
        #pragma unroll
        for (int i = 0; i < 8; ++i) {
            int e = tid + i * 256;                  // 0..2047 chunks
            int blk = e >> 5, l = e & 31;
            int a_l = blk >> 3, c8l = blk & 7;
            uint4 v = *reinterpret_cast<const uint4*>(&st[blk * 128 + l * 4]);
            reinterpret_cast<uint4*>(g_h)[
                ((size_t)((m0 >> 4) + a_l) * 64 + (n0 >> 3) + c8l) * 32 + l] = v;
        }
    } else {
        // ---- direct fp32 row-major epilogue (gemm2) ----
        #pragma unroll
        for (int mt = 0; mt < MT; ++mt) {
            #pragma unroll
            for (int nt = 0; nt < 4; ++nt) {
                int gc = n0 + warp_n + nt * 8 + t4 * 2;
                float2 bv = *reinterpret_cast<const float2*>(bias + gc);
                #pragma unroll
                for (int hh = 0; hh < 2; ++hh) {
                    int gr = m0 + warp_m + mt * 16 + g + hh * 8;
                    if (gr >= N_NODES) continue;
                    float2 o;
                    o.x = acc[mt][nt][hh * 2 + 0] + bv.x;
                    o.y = acc[mt][nt][hh * 2 + 1] + bv.y;
                    *reinterpret_cast<float2*>(Cout + (size_t)gr * F_OUT + gc) = o;
                }
            }
        }
    }
}

// ---------------------------------------------------------------------------
// order: memset(agg) -> scatter -> prep -> gemm1 -> gemm2
// Inputs: nodes, edge_attr, senders, receivers, W1, b1, W2, b2
// ---------------------------------------------------------------------------
extern "C" void kernel_launch(void* const* d_in, const int* in_sizes, int n_in,
                              void* d_out, int out_size)
{
    const float*  nodes     = (const float*)d_in[0];
    const float4* edge_attr = (const float4*)d_in[1];
    const int*    receivers = (const int*)d_in[3];
    const float*  W1        = (const float*)d_in[4];
    const float*  b1        = (const float*)d_in[5];
    const float*  W2        = (const float*)d_in[6];
    const float*  b2        = (const float*)d_in[7];
    float* out = (float*)d_out;

    uint32_t *w1t = nullptr, *w2t = nullptr, *gA = nullptr, *gh = nullptr;
    float* gagg = nullptr;
    cudaGetSymbolAddress((void**)&w1t,  g_W1t);
    cudaGetSymbolAddress((void**)&w2t,  g_W2t);
    cudaGetSymbolAddress((void**)&gA,   g_A);
    cudaGetSymbolAddress((void**)&gh,   g_h);
    cudaGetSymbolAddress((void**)&gagg, g_agg);

    constexpr int SMEM = 3 * (128 + 64) * 32 * 4;   // 73,728 B (both gemms)

    static bool attr_set = false;
    if (!attr_set) {
        cudaFuncSetAttribute(gemm_frag_kernel<true>,
                             cudaFuncAttributeMaxDynamicSharedMemorySize, SMEM);
        cudaFuncSetAttribute(gemm_frag_kernel<false>,
                             cudaFuncAttributeMaxDynamicSharedMemorySize, SMEM);
        attr_set = true;
    }

    // 1) zero agg
    cudaMemsetAsync(gagg, 0, (size_t)N_NODES * F_E * sizeof(float));

    // 2) scatter
    {
        long long total = (long long)N_EDGES * 32;
        int blocks = (int)((total + 255) / 256);
        scatter_edges_kernel<<<blocks, 256>>>(edge_attr, receivers);
    }
    // 3) prep (coalesced FRAG builds)
    prep_kernel<<<PREP_BLKS, 256>>>(nodes, W1, W2);
    // 4) gemm1: grid (8, 391)
    {
        dim3 grid(HIDDEN / 64, (N_NODES + 127) / 128);
        gemm_frag_kernel<true><<<grid, 256, SMEM>>>(gA, w1t, b1, nullptr);
    }
    // 5) gemm2: grid (2, 391)
    {
        dim3 grid(F_OUT / 64, (N_NODES + 127) / 128);
        gemm_frag_kernel<false><<<grid, 256, SMEM>>>(gh, w2t, b2, out);
    }
}

// round 16
// speedup vs baseline: 1.0347x; 1.0347x over previous
#include <cuda_runtime.h>
#include <cstdint>

#define N_NODES 50000
#define N_EDGES 800000
#define F_X 128
#define F_E 128
#define HIDDEN 512
#define F_OUT 128
#define M_BLKS 3128                    // 50048 rows: pads 50000 to 128-row CTAs

// ---------------- scratch (static device globals; no runtime alloc) --------
// FRAG-A layout: word(r,c) = ((r>>4)*(K/8) + (c>>3))*128
//                            + (4*(r&7)+(c&3))*4 + ((c>>2)&1)*2 + ((r>>3)&1)
// FRAG-B layout: word(n,k) = ((n>>3)*(K/16) + (k>>4))*128
//                            + (4*(n&7)+(k&3))*4 + ((k>>3)&1)*2 + ((k>>2)&1)
__device__ float    g_agg[(size_t)N_NODES * F_E];                 // 25.6 MB
__device__ uint32_t g_A[(size_t)M_BLKS * 32 * 128];               // 51.3 MB, K=256
__device__ uint32_t g_h[(size_t)M_BLKS * 64 * 128];               // 102.5 MB, K=512
__device__ uint32_t g_W1t[(size_t)HIDDEN * (F_E + F_X)];          // FRAG-B K=256
__device__ uint32_t g_W2t[(size_t)F_OUT * HIDDEN];                // FRAG-B K=512

__device__ __forceinline__ uint32_t f2tf32(float f) {
    uint32_t r; asm("cvt.rna.tf32.f32 %0, %1;" : "=r"(r) : "f"(f)); return r;
}
__device__ __forceinline__ uint32_t smem_u32(const void* p) {
    uint32_t a;
    asm("{ .reg .u64 t; cvta.to.shared.u64 t, %1; cvt.u32.u64 %0, t; }"
        : "=r"(a) : "l"(p));
    return a;
}

// ---------------------------------------------------------------------------
// launch #1: zero agg buffer (kernel, not memset: keeps ncu capture on gemm1)
// ---------------------------------------------------------------------------
__global__ void zero_agg_kernel() {
    int i = blockIdx.x * blockDim.x + threadIdx.x;
    const int n4 = N_NODES * F_E / 4;
    float4* p = reinterpret_cast<float4*>(g_agg);
    if (i < n4) p[i] = make_float4(0.f, 0.f, 0.f, 0.f);
}

// ---------------------------------------------------------------------------
// launch #2: scatter-add, one warp per edge, red.global.add.v4.f32 (DRAM floor)
// ---------------------------------------------------------------------------
__global__ void __launch_bounds__(256) scatter_edges_kernel(
    const float4* __restrict__ edge_attr, const int* __restrict__ receivers)
{
    int gt = blockIdx.x * blockDim.x + threadIdx.x;
    int edge = gt >> 5;
    int lane = gt & 31;
    if (edge >= N_EDGES) return;

    int r = __ldg(receivers + edge);
    float4 v = edge_attr[(size_t)edge * 32 + lane];
    float* dst = g_agg + (size_t)r * F_E + lane * 4;
    asm volatile("red.global.add.v4.f32 [%0], {%1,%2,%3,%4};"
                 :: "l"(dst), "f"(v.x), "f"(v.y), "f"(v.z), "f"(v.w)
                 : "memory");
}

// ---------------------------------------------------------------------------
// launch #3: prep v2 — fully-coalesced FRAG builds (kept from R14).
//  blocks [0, 3125)        : A tile transpose — 16 rows x 256 cols per CTA
//  blocks [3125, 3253)     : W1 FRAG-B chunks (256/CTA)
//  blocks [3253, 3317)     : W2 FRAG-B chunks (256/CTA)
// ---------------------------------------------------------------------------
#define PREP_ABLK  3125
#define PREP_W1BLK 128           // 32768 chunks / 256
#define PREP_W2BLK 64            // 16384 chunks / 256
#define PREP_BLKS  (PREP_ABLK + PREP_W1BLK + PREP_W2BLK)

__global__ void __launch_bounds__(256) prep_kernel(
    const float* __restrict__ nodes,
    const float* __restrict__ W1, const float* __restrict__ W2)
{
    int blk = blockIdx.x;
    int tid = threadIdx.x;

    if (blk < PREP_ABLK) {
        __shared__ uint32_t s[16 * 260];       // stride 260: LDS bank = 4g+t4
        int a = blk;
        #pragma unroll
        for (int i = 0; i < 4; ++i) {
            int e = tid + i * 256;             // 0..1023 float4
            int r = e >> 6, c = (e & 63) * 4;
            const float* src = (c < F_E)
                ? (g_agg + (size_t)(a * 16 + r) * F_E + c)
                : (nodes + (size_t)(a * 16 + r) * F_X + (c - F_E));
            float4 v = *reinterpret_cast<const float4*>(src);
            uint4 t;
            t.x = f2tf32(v.x); t.y = f2tf32(v.y);
            t.z = f2tf32(v.z); t.w = f2tf32(v.w);
            *reinterpret_cast<uint4*>(&s[r * 260 + c]) = t;
        }
        __syncthreads();
        #pragma unroll
        for (int i = 0; i < 4; ++i) {
            int e = tid + i * 256;             // 0..1023 chunks
            int b = e >> 5, l = e & 31;
            int gg = l >> 2, t4 = l & 3;
            int c = b * 8 + t4;
            uint4 t;
            t.x = s[gg * 260 + c];
            t.y = s[(gg + 8) * 260 + c];
            t.z = s[gg * 260 + c + 4];
            t.w = s[(gg + 8) * 260 + c + 4];
            reinterpret_cast<uint4*>(g_A)[(size_t)a * 1024 + e] = t;
        }
    } else if (blk < PREP_ABLK + PREP_W1BLK) {
        int idx = (blk - PREP_ABLK) * 256 + tid;      // 0..32767
        int cb = idx >> 5, l = idx & 31;
        int n8 = cb >> 4, kb = cb & 15;               // K/16 = 16
        int n = n8 * 8 + (l >> 2), t4 = l & 3;
        int k0 = kb * 16 + t4;
        uint4 t;
        t.x = f2tf32(W1[(size_t)(k0     ) * HIDDEN + n]);
        t.y = f2tf32(W1[(size_t)(k0 +  4) * HIDDEN + n]);
        t.z = f2tf32(W1[(size_t)(k0 +  8) * HIDDEN + n]);
        t.w = f2tf32(W1[(size_t)(k0 + 12) * HIDDEN + n]);
        reinterpret_cast<uint4*>(g_W1t)[idx] = t;
    } else {
        int idx = (blk - PREP_ABLK - PREP_W1BLK) * 256 + tid;  // 0..16383
        int cb = idx >> 5, l = idx & 31;
        int n8 = cb >> 5, kb = cb & 31;               // K/16 = 32
        int n = n8 * 8 + (l >> 2), t4 = l & 3;
        int k0 = kb * 16 + t4;
        uint4 t;
        t.x = f2tf32(W2[(size_t)(k0     ) * F_OUT + n]);
        t.y = f2tf32(W2[(size_t)(k0 +  4) * F_OUT + n]);
        t.z = f2tf32(W2[(size_t)(k0 +  8) * F_OUT + n]);
        t.w = f2tf32(W2[(size_t)(k0 + 12) * F_OUT + n]);
        reinterpret_cast<uint4*>(g_W2t)[idx] = t;
    }
}

// ---------------------------------------------------------------------------
// launches #4/#5: cp.async 3-stage tf32 mma GEMM on FRAG-major operands.
// (R13 kernel, byte-identical mainloop + direct epilogues — the 240.1us config)
// Unified shape: BM=128, BN=64, BK=32; 8 warps 4m x 2n (warp 32x32), MT=2.
// 3 CTAs/SM (launch_bounds(256,3), 73.7 KB smem).
// L1=true : K=256, A=g_A, out=g_h (FRAG-A K=512) bias+ReLU. grid (8,391).
// L1=false: K=512, A=g_h, out=Cout fp32 row-major bias.     grid (2,391).
// ---------------------------------------------------------------------------
template <bool L1>
__global__ void __launch_bounds__(256, 3)
gemm_frag_kernel(const uint32_t* __restrict__ Aglob,
                 const uint32_t* __restrict__ Bglob,
                 const float* __restrict__ bias,
                 float* __restrict__ Cout)
{
    constexpr int K   = L1 ? 256 : 512;
    constexpr int BN  = 64;
    constexpr int MT  = 2;
    constexpr int NTILES = K / 32;
    constexpr int A_STW  = 128 * 32;                // 4096 words
    constexpr int B_STW  = BN * 32;                 // 2048 words
    constexpr int STW    = A_STW + B_STW;           // 6144 words / stage
    constexpr int KB8    = K / 8;
    constexpr int KB16   = K / 16;

    extern __shared__ uint32_t smem[];
    const uint32_t sbase = smem_u32(smem);

    const int tid  = threadIdx.x;
    const int lane = tid & 31;
    const int warp = tid >> 5;
    const int m0 = blockIdx.y * 128;
    const int n0 = blockIdx.x * BN;
    const int warp_m = (warp >> 1) * 32;
    const int warp_n = (warp & 1) * 32;
    const int g  = lane >> 2;
    const int t4 = lane & 3;

    float acc[MT][4][4];
    #pragma unroll
    for (int mt = 0; mt < MT; ++mt)
        #pragma unroll
        for (int nt = 0; nt < 4; ++nt)
            #pragma unroll
            for (int i = 0; i < 4; ++i) acc[mt][nt][i] = 0.f;

    auto issue = [&](int tile, int slot) {
        const int kb8  = tile * 4;
        const int kb16 = tile * 2;
        uint32_t ab = sbase + (uint32_t)(slot * STW) * 4;
        uint32_t bb = ab + A_STW * 4;
        #pragma unroll
        for (int i = 0; i < 4; ++i) {                 // A: 1024 chunks
            int e = tid + i * 256;
            int a_l = e >> 7, b_l = (e >> 5) & 3, l = e & 31;
            const uint32_t* src = Aglob +
                ((size_t)((m0 >> 4) + a_l) * KB8 + kb8 + b_l) * 128 + l * 4;
            asm volatile("cp.async.cg.shared.global [%0], [%1], 16;"
                :: "r"(ab + (uint32_t)(((a_l * 4 + b_l) * 32 + l) * 16)),
                   "l"(src) : "memory");
        }
        #pragma unroll
        for (int i = 0; i < 2; ++i) {                 // B: 512 chunks
            int e = tid + i * 256;
            int n_l = e >> 6, p = (e >> 5) & 1, l = e & 31;
            const uint32_t* src = Bglob +
                ((size_t)((n0 >> 3) + n_l) * KB16 + kb16 + p) * 128 + l * 4;
            asm volatile("cp.async.cg.shared.global [%0], [%1], 16;"
                :: "r"(bb + (uint32_t)(((n_l * 2 + p) * 32 + l) * 16)),
                   "l"(src) : "memory");
        }
    };

    issue(0, 0); asm volatile("cp.async.commit_group;" ::: "memory");
    issue(1, 1); asm volatile("cp.async.commit_group;" ::: "memory");

    for (int it = 0; it < NTILES; ++it) {
        asm volatile("cp.async.wait_group 1;" ::: "memory");
        __syncthreads();
        // single barrier: all warps finished compute(it-1); slot (it+2)%3
        // == (it-1)%3 is safe to overwrite.
        if (it + 2 < NTILES) issue(it + 2, (it + 2) % 3);
        asm volatile("cp.async.commit_group;" ::: "memory");

        const uint4* As4 = reinterpret_cast<const uint4*>(smem + (it % 3) * STW);
        const uint4* Bs4 = As4 + A_STW / 4;

        #pragma unroll
        for (int p = 0; p < 2; ++p) {                  // k16 pair
            uint4 bfr[4];
            #pragma unroll
            for (int nt = 0; nt < 4; ++nt) {
                int n_l = (warp_n >> 3) + nt;
                bfr[nt] = Bs4[(n_l * 2 + p) * 32 + lane];
            }
            #pragma unroll
            for (int half = 0; half < 2; ++half) {
                const int ks = p * 2 + half;
                uint4 afr[MT];
                #pragma unroll
                for (int mt = 0; mt < MT; ++mt) {
                    int a_l = (warp_m >> 4) + mt;
                    afr[mt] = As4[(a_l * 4 + ks) * 32 + lane];
                }
                #pragma unroll
                for (int mt = 0; mt < MT; ++mt)
                    #pragma unroll
                    for (int nt = 0; nt < 4; ++nt) {
                        uint32_t b0 = half ? bfr[nt].z : bfr[nt].x;
                        uint32_t b1 = half ? bfr[nt].w : bfr[nt].y;
                        asm volatile(
                            "mma.sync.aligned.m16n8k8.row.col.f32.tf32.tf32.f32 "
                            "{%0,%1,%2,%3}, {%4,%5,%6,%7}, {%8,%9}, {%0,%1,%2,%3};"
                            : "+f"(acc[mt][nt][0]), "+f"(acc[mt][nt][1]),
                              "+f"(acc[mt][nt][2]), "+f"(acc[mt][nt][3])
                            : "r"(afr[mt].x), "r"(afr[mt].y),
                              "r"(afr[mt].z), "r"(afr[mt].w),
                              "r"(b0), "r"(b1));
                    }
            }
        }
    }

    // ---- direct epilogues (R13) ----
    #pragma unroll
    for (int mt = 0; mt < MT; ++mt) {
        #pragma unroll
        for (int nt = 0; nt < 4; ++nt) {
            int gc = n0 + warp_n + nt * 8 + t4 * 2;
            float2 bv = *reinterpret_cast<const float2*>(bias + gc);
            #pragma unroll
            for (int hh = 0; hh < 2; ++hh) {
                int gr = m0 + warp_m + mt * 16 + g + hh * 8;
                if (gr >= N_NODES) continue;
                float ox = acc[mt][nt][hh * 2 + 0] + bv.x;
                float oy = acc[mt][nt][hh * 2 + 1] + bv.y;
                if (L1) {
                    // store into g_h FRAG-A (K=512): two scalar words
                    uint32_t tx = f2tf32(fmaxf(ox, 0.f));
                    uint32_t ty = f2tf32(fmaxf(oy, 0.f));
                    size_t base = ((size_t)(gr >> 4) * 64 + (gc >> 3)) * 128;
                    int wr = (gr >> 3) & 1;
                    size_t a0 = base + (4 * (gr & 7) + (gc & 3)) * 4
                                     + ((gc >> 2) & 1) * 2 + wr;
                    int gc1 = gc + 1;
                    size_t a1 = base + (4 * (gr & 7) + (gc1 & 3)) * 4
                                     + ((gc1 >> 2) & 1) * 2 + wr;
                    g_h[a0] = tx;
                    g_h[a1] = ty;
                } else {
                    float2 o = make_float2(ox, oy);
                    *reinterpret_cast<float2*>(Cout + (size_t)gr * F_OUT + gc) = o;
                }
            }
        }
    }
}

// ---------------------------------------------------------------------------
// order: zero(1) -> scatter(2) -> prep(3) -> gemm1(4) -> gemm2(5)
// (#4 is the ncu-captured launch -> gemm1 profile this round)
// Inputs: nodes, edge_attr, senders, receivers, W1, b1, W2, b2
// ---------------------------------------------------------------------------
extern "C" void kernel_launch(void* const* d_in, const int* in_sizes, int n_in,
                              void* d_out, int out_size)
{
    const float*  nodes     = (const float*)d_in[0];
    const float4* edge_attr = (const float4*)d_in[1];
    const int*    receivers = (const int*)d_in[3];
    const float*  W1        = (const float*)d_in[4];
    const float*  b1        = (const float*)d_in[5];
    const float*  W2        = (const float*)d_in[6];
    const float*  b2        = (const float*)d_in[7];
    float* out = (float*)d_out;

    uint32_t *w1t = nullptr, *w2t = nullptr, *gA = nullptr, *gh = nullptr;
    cudaGetSymbolAddress((void**)&w1t,  g_W1t);
    cudaGetSymbolAddress((void**)&w2t,  g_W2t);
    cudaGetSymbolAddress((void**)&gA,   g_A);
    cudaGetSymbolAddress((void**)&gh,   g_h);

    constexpr int SMEM = 3 * (128 + 64) * 32 * 4;   // 73,728 B (both gemms)

    static bool attr_set = false;
    if (!attr_set) {
        cudaFuncSetAttribute(gemm_frag_kernel<true>,
                             cudaFuncAttributeMaxDynamicSharedMemorySize, SMEM);
        cudaFuncSetAttribute(gemm_frag_kernel<false>,
                             cudaFuncAttributeMaxDynamicSharedMemorySize, SMEM);
        attr_set = true;
    }

    // 1) zero agg
    zero_agg_kernel<<<(N_NODES * F_E / 4 + 255) / 256, 256>>>();
    // 2) scatter
    {
        long long total = (long long)N_EDGES * 32;
        int blocks = (int)((total + 255) / 256);
        scatter_edges_kernel<<<blocks, 256>>>(edge_attr, receivers);
    }
    // 3) prep (coalesced FRAG builds)
    prep_kernel<<<PREP_BLKS, 256>>>(nodes, W1, W2);
    // 4) gemm1: grid (8, 391)
    {
        dim3 grid(HIDDEN / 64, (N_NODES + 127) / 128);
        gemm_frag_kernel<true><<<grid, 256, SMEM>>>(gA, w1t, b1, nullptr);
    }
    // 5) gemm2: grid (2, 391)
    {
        dim3 grid(F_OUT / 64, (N_NODES + 127) / 128);
        gemm_frag_kernel<false><<<grid, 256, SMEM>>>(gh, w2t, b2, out);
    }
}